// round 6
// baseline (speedup 1.0000x reference)
#include <cuda_runtime.h>
#include <cuda_bf16.h>
#include <cstdint>

// Embedding gather: out[row, :] = table[token_ids[row], :]
//   table: [50257, 768] fp32 (d_in[1])
//   ids:   [16384]  int64 OR int32 (d_in[0]) -- width auto-detected
//   out:   [16384, 768] fp32
//
// R5: resubmit of R4 (container infra failure, kernel untested).
// sm_100a requires 256-bit vectors (.v8.b32) for L2 eviction-priority hints.
// Table reads: evict_last (pin rows in L2 across graph replays).
// Output stores: evict_first (write-only stream must not displace table).
// Goal: steady-state DRAM ~= the 48MB compulsory write (~8-9us floor).

#define VOCAB          50257
#define D_MODEL        768
#define U32_PER_ROW    D_MODEL          // 768 u32 per row
#define CHUNKS_PER_ROW 96               // 96 x 32B = 3072B
#define N_ROWS         16384
#define ROWS_PER_CTA   8
#define THREADS        192              // 2 row-slots x 96 lanes
#define ROWS_PER_SLOT  (ROWS_PER_CTA / 2)

// Hot int32 token array (64 KiB).
__device__ int g_tokens[N_ROWS];

__device__ __forceinline__ void ldg256_evict_last(const unsigned* p, unsigned v[8]) {
    asm volatile("ld.global.nc.L2::evict_last.v8.b32 {%0,%1,%2,%3,%4,%5,%6,%7}, [%8];"
                 : "=r"(v[0]), "=r"(v[1]), "=r"(v[2]), "=r"(v[3]),
                   "=r"(v[4]), "=r"(v[5]), "=r"(v[6]), "=r"(v[7])
                 : "l"(p));
}

__device__ __forceinline__ void stg256_evict_first(unsigned* p, const unsigned v[8]) {
    asm volatile("st.global.L2::evict_first.v8.b32 [%0], {%1,%2,%3,%4,%5,%6,%7,%8};"
                 :: "l"(p),
                    "r"(v[0]), "r"(v[1]), "r"(v[2]), "r"(v[3]),
                    "r"(v[4]), "r"(v[5]), "r"(v[6]), "r"(v[7])
                 : "memory");
}

// Width-detect + convert. All blocks read the SAME first 512 u64 words
// (4 KiB, L2 broadcast) so every block reaches the same verdict:
//   int64 layout: every u64 word is a token < VOCAB.
//   int32 layout: words pack two tokens; P(all 512 high halves zero)
//                 ~ (1/VOCAB)^512 ~= 0.
// Sample is in-bounds under both layouts (int32 buffer = 8192 u64 words).
__global__ void convert_ids_kernel(const unsigned long long* __restrict__ ids_u64) {
    bool is64 = true;
    #pragma unroll 4
    for (int i = threadIdx.x & 127; i < 512; i += 128) {
        if (ids_u64[i] >= (unsigned long long)VOCAB) is64 = false;
    }
    is64 = __all_sync(0xFFFFFFFFu, is64);

    const int idx = blockIdx.x * blockDim.x + threadIdx.x;
    if (idx < N_ROWS) {
        int tok;
        if (is64) tok = (int)((const long long*)ids_u64)[idx];
        else      tok = ((const int*)ids_u64)[idx];
        g_tokens[idx] = tok;
    }
}

// 8 rows per CTA. Thread t: lane = t%96 (32B chunk in row), slot = t/96.
// Rows handled: rbase = row0 + slot*4, j=0..3. 4 independent 256-bit pinned
// loads (MLP=4, 128B in flight per thread), then 4 evict-first 256-bit
// stores. All indexing 32-bit (offsets < 2^26).
__global__ __launch_bounds__(THREADS)
void embedding_gather_kernel(const unsigned* __restrict__ table,
                             unsigned* __restrict__ out) {
    const int row0 = blockIdx.x * ROWS_PER_CTA;
    const int lane = threadIdx.x % CHUNKS_PER_ROW;
    const int slot = threadIdx.x / CHUNKS_PER_ROW;
    const int rbase = row0 + slot * ROWS_PER_SLOT;
    const int coff = lane * 8;                     // u32 offset of 32B chunk

    int off[ROWS_PER_SLOT];
    #pragma unroll
    for (int j = 0; j < ROWS_PER_SLOT; j++)
        off[j] = g_tokens[rbase + j] * U32_PER_ROW + coff;

    unsigned v[ROWS_PER_SLOT][8];
    #pragma unroll
    for (int j = 0; j < ROWS_PER_SLOT; j++)
        ldg256_evict_last(table + off[j], v[j]);

    unsigned* dst = out + rbase * U32_PER_ROW + coff;
    #pragma unroll
    for (int j = 0; j < ROWS_PER_SLOT; j++)
        stg256_evict_first(dst + j * U32_PER_ROW, v[j]);
}

extern "C" void kernel_launch(void* const* d_in, const int* in_sizes, int n_in,
                              void* d_out, int out_size) {
    const void*     ids   = d_in[0];
    const unsigned* table = (const unsigned*)d_in[1];
    unsigned*       out   = (unsigned*)d_out;

    convert_ids_kernel<<<N_ROWS / 256, 256>>>((const unsigned long long*)ids);
    embedding_gather_kernel<<<N_ROWS / ROWS_PER_CTA, THREADS>>>(table, out);
}